// round 6
// baseline (speedup 1.0000x reference)
#include <cuda_runtime.h>
#include <math.h>
#include <float.h>

#define BS 16
#define CH 64
#define NC 81
#define HW 65536          // 256*256
#define FG_STCH 1
#define JCNT (CH - FG_STCH)            // 63
#define SPLIT 4                        // chunks per (b,c) row
#define CHUNK (HW / 4 / SPLIT)         // float4 per chunk = 4096
#define NBLK (BS * CH * SPLIT)         // 4096 blocks
#define NLOSS_BLK 126                  // 8 items/block * 126 = 1008 items
#define NITEMS (BS * JCNT)             // 1008
#define WPB 8                          // warps per block

// Scratch (no cudaMalloc allowed)
__device__ float  g_maxprob_part[NBLK];
__device__ float4 g_scratch[NITEMS];   // per item: (ce, iou_el, signed_wght, mpIdx as int)
__device__ int    g_count;             // block completions (-> NBLK); reset by last block

// ---------------------------------------------------------------------------
// Single fused kernel, no resident waiters:
//   phase 1 (all 4096 blocks): stream one 64KB chunk -> partial max.
//   phase 2 (blocks 0..125): maxprob-independent loss pre-work, packed into
//           g_scratch (overlaps later streaming waves), then EXIT like
//           everyone else — no SM slot is held.
//   phase 3: the last block to increment g_count (after threadfence) performs
//           the entire final pass from L2-warm scratch: ~1-1.5us tail.
// ---------------------------------------------------------------------------
__global__ __launch_bounds__(256) void fused_kernel(
    const float4* __restrict__ p,            // pred_mask_prob as float4
    const float* __restrict__ cls_logits,    // (bs, ch, C)
    const float* __restrict__ iou_scores,    // (bs, ch, 1)
    const int*   __restrict__ target_ids,    // (bs, ch)
    const int*   __restrict__ map_indices,   // (bs, 2, ch)
    const float* __restrict__ map_ious,      // (bs, ch)
    const float* __restrict__ rand_vals,     // (bs, ch)
    float* __restrict__ out)                 // [iou_loss, cls_loss]
{
    const int blk  = blockIdx.x;
    const int warp = threadIdx.x >> 5;
    const int lane = threadIdx.x & 31;

    // ---------------- phase 1: streaming maxprob chunk ----------------
    {
        const float4* base = p + (size_t)blk * CHUNK;
        float m0 = -FLT_MAX, m1 = -FLT_MAX, m2 = -FLT_MAX, m3 = -FLT_MAX;
#pragma unroll
        for (int i = 0; i < CHUNK / (256 * 4); i++) {
            const int bi = i * 256 * 4 + threadIdx.x;
            float4 v0 = __ldcs(&base[bi]);
            float4 v1 = __ldcs(&base[bi + 256]);
            float4 v2 = __ldcs(&base[bi + 512]);
            float4 v3 = __ldcs(&base[bi + 768]);
            m0 = fmaxf(m0, fmaxf(fmaxf(v0.x, v0.y), fmaxf(v0.z, v0.w)));
            m1 = fmaxf(m1, fmaxf(fmaxf(v1.x, v1.y), fmaxf(v1.z, v1.w)));
            m2 = fmaxf(m2, fmaxf(fmaxf(v2.x, v2.y), fmaxf(v2.z, v2.w)));
            m3 = fmaxf(m3, fmaxf(fmaxf(v3.x, v3.y), fmaxf(v3.z, v3.w)));
        }
        float m = fmaxf(fmaxf(m0, m1), fmaxf(m2, m3));

#pragma unroll
        for (int o = 16; o > 0; o >>= 1)
            m = fmaxf(m, __shfl_xor_sync(0xFFFFFFFFu, m, o));

        __shared__ float sm[WPB];
        if (lane == 0) sm[warp] = m;
        __syncthreads();
        if (threadIdx.x < WPB) {
            m = sm[threadIdx.x];
#pragma unroll
            for (int o = WPB / 2; o > 0; o >>= 1)
                m = fmaxf(m, __shfl_xor_sync(0xFFu, m, o));
            if (threadIdx.x == 0) g_maxprob_part[blk] = m;
        }
    }

    // ---------------- phase 2: loss pre-work (first 126 blocks) -------------
    if (blk < NLOSS_BLK) {
        const int item = blk * WPB + warp;   // 0..1007 exact
        const int b = item / JCNT;
        const int j = FG_STCH + (item % JCNT);

        const int pj  = map_indices[b * 2 * CH + 0 * CH + j];
        const int gj  = map_indices[b * 2 * CH + 1 * CH + j];
        const int tid = target_ids[b * CH + gj];
        const int cls = max(0, tid - FG_STCH + 1);

        const float iou = map_ious[b * CH + j];
        const float rnd = rand_vals[b * CH + j];
        const float wght_base = (iou < 0.2f) ? 1.0f : 2.0f;
        // sign bit encodes (rnd < 0.9): negative => removable
        const float signed_w = (rnd < 0.9f) ? -wght_base : wght_base;

        const float preds_iou = iou_scores[b * CH + pj];
        const float y = fabsf(preds_iou - iou);
        const float iou_el = (y < 0.1f) ? (y * y * 5.0f) : (y - 0.05f);

        // warp-parallel log-softmax over C=81
        const float* row = cls_logits + (size_t)(b * CH + pj) * NC;
        const float x0 = row[lane];
        const float x1 = row[lane + 32];
        const float x2 = (lane < NC - 64) ? row[lane + 64] : -FLT_MAX;

        float mx = fmaxf(fmaxf(x0, x1), x2);
#pragma unroll
        for (int o = 16; o > 0; o >>= 1)
            mx = fmaxf(mx, __shfl_xor_sync(0xFFFFFFFFu, mx, o));

        float s = expf(x0 - mx) + expf(x1 - mx);
        if (lane < NC - 64) s += expf(x2 - mx);
#pragma unroll
        for (int o = 16; o > 0; o >>= 1)
            s += __shfl_xor_sync(0xFFFFFFFFu, s, o);

        if (lane == 0) {
            const float ce = -(row[cls] - mx - logf(s));   // w[cls] == 1
            float4 scr;
            scr.x = ce;
            scr.y = iou_el;
            scr.z = signed_w;
            scr.w = __int_as_float(b * CH + pj);           // mp index
            g_scratch[item] = scr;
        }
    }

    // ---------------- completion + elect last block ----------------
    __threadfence();          // make this thread's global writes visible
    __syncthreads();

    __shared__ bool is_last;
    if (threadIdx.x == 0) {
        const int prev = atomicAdd(&g_count, 1);
        is_last = (prev == NBLK - 1);
    }
    __syncthreads();
    if (!is_last) return;

    // ---------------- phase 3: final pass (one block, all data L2-warm) -----
    __threadfence();          // order subsequent reads after counter observation

    float v0 = 0.0f, v1 = 0.0f, v2 = 0.0f;
    for (int i = threadIdx.x; i < NITEMS; i += 256) {
        const float4 scr = *(const float4*)&g_scratch[i];   // L2-warm
        const int mpIdx = __float_as_int(scr.w);
        const float* mpp = &g_maxprob_part[mpIdx * SPLIT];
        const float mp = fmaxf(fmaxf(__ldcg(&mpp[0]), __ldcg(&mpp[1])),
                               fmaxf(__ldcg(&mpp[2]), __ldcg(&mpp[3])));
        const bool remove = (mp < 0.1f) && (scr.z < 0.0f);
        const float wght = remove ? 0.0f : fabsf(scr.z);
        v0 += wght;
        v1 += scr.y * wght;
        v2 += scr.x * wght;
    }

#pragma unroll
    for (int o = 16; o > 0; o >>= 1) {
        v0 += __shfl_xor_sync(0xFFFFFFFFu, v0, o);
        v1 += __shfl_xor_sync(0xFFFFFFFFu, v1, o);
        v2 += __shfl_xor_sync(0xFFFFFFFFu, v2, o);
    }

    __shared__ float r0[WPB], r1[WPB], r2[WPB];
    if (lane == 0) { r0[warp] = v0; r1[warp] = v1; r2[warp] = v2; }
    __syncthreads();

    if (warp == 0) {
        float a0 = (lane < WPB) ? r0[lane] : 0.0f;
        float a1 = (lane < WPB) ? r1[lane] : 0.0f;
        float a2 = (lane < WPB) ? r2[lane] : 0.0f;
#pragma unroll
        for (int o = WPB / 2; o > 0; o >>= 1) {
            a0 += __shfl_xor_sync(0xFFFFFFFFu, a0, o);
            a1 += __shfl_xor_sync(0xFFFFFFFFu, a1, o);
            a2 += __shfl_xor_sync(0xFFFFFFFFu, a2, o);
        }
        if (lane == 0) {
            const float wsum = a0 + 0.0001f;
            out[0] = a1 / wsum;   // iou_loss
            out[1] = a2 / wsum;   // cls_loss
            g_count = 0;          // reset for next graph replay
        }
    }
}

// ---------------------------------------------------------------------------
extern "C" void kernel_launch(void* const* d_in, const int* in_sizes, int n_in,
                              void* d_out, int out_size) {
    const float* cls_logits     = (const float*)d_in[0];
    const float* iou_scores     = (const float*)d_in[1];
    const int*   target_ids     = (const int*)  d_in[2];
    const int*   map_indices    = (const int*)  d_in[3];
    const float* map_ious       = (const float*)d_in[4];
    const float* pred_mask_prob = (const float*)d_in[5];
    const float* rand_vals      = (const float*)d_in[6];
    float* out = (float*)d_out;

    fused_kernel<<<NBLK, 256>>>((const float4*)pred_mask_prob,
                                cls_logits, iou_scores, target_ids,
                                map_indices, map_ious, rand_vals, out);
}

// round 7
// speedup vs baseline: 1.0457x; 1.0457x over previous
#include <cuda_runtime.h>
#include <math.h>
#include <float.h>

#define BS 16
#define CH 64
#define NC 81
#define HW 65536          // 256*256
#define FG_STCH 1
#define JCNT (CH - FG_STCH)            // 63
#define SPLIT 4                        // chunks per (b,c) row
#define CHUNK (HW / 4 / SPLIT)         // float4 per chunk = 4096
#define NBLK (BS * CH * SPLIT)         // 4096 blocks
#define NITEMS (BS * JCNT)             // 1008
#define NLOSS_BLK 126                  // 8 items/block (warp-per-item)
#define WPB 8

// Scratch (no cudaMalloc allowed)
__device__ float g_maxprob_part[NBLK];
__device__ float g_partial[NLOSS_BLK * 3];
__device__ int   g_loss_count;         // loss block completions; reset by last block

// ---------------------------------------------------------------------------
// Kernel A (UNCHANGED from R3 — proven ~37.5us, ~6.8TB/s): partial max over
// one 64KB chunk per block. Pure, homogeneous streaming.
// ---------------------------------------------------------------------------
__global__ __launch_bounds__(256) void maxprob_kernel(const float4* __restrict__ p) {
    const int blk = blockIdx.x;                    // 0..4095
    const float4* base = p + (size_t)blk * CHUNK;

    float m0 = -FLT_MAX, m1 = -FLT_MAX, m2 = -FLT_MAX, m3 = -FLT_MAX;
#pragma unroll
    for (int i = 0; i < CHUNK / (256 * 4); i++) {
        const int bi = i * 256 * 4 + threadIdx.x;
        float4 v0 = __ldcs(&base[bi]);
        float4 v1 = __ldcs(&base[bi + 256]);
        float4 v2 = __ldcs(&base[bi + 512]);
        float4 v3 = __ldcs(&base[bi + 768]);
        m0 = fmaxf(m0, fmaxf(fmaxf(v0.x, v0.y), fmaxf(v0.z, v0.w)));
        m1 = fmaxf(m1, fmaxf(fmaxf(v1.x, v1.y), fmaxf(v1.z, v1.w)));
        m2 = fmaxf(m2, fmaxf(fmaxf(v2.x, v2.y), fmaxf(v2.z, v2.w)));
        m3 = fmaxf(m3, fmaxf(fmaxf(v3.x, v3.y), fmaxf(v3.z, v3.w)));
    }
    float m = fmaxf(fmaxf(m0, m1), fmaxf(m2, m3));

#pragma unroll
    for (int o = 16; o > 0; o >>= 1)
        m = fmaxf(m, __shfl_xor_sync(0xFFFFFFFFu, m, o));

    __shared__ float sm[8];
    if ((threadIdx.x & 31) == 0) sm[threadIdx.x >> 5] = m;
    __syncthreads();
    if (threadIdx.x < 8) {
        m = sm[threadIdx.x];
#pragma unroll
        for (int o = 4; o > 0; o >>= 1)
            m = fmaxf(m, __shfl_xor_sync(0xFFu, m, o));
        if (threadIdx.x == 0) g_maxprob_part[blk] = m;
    }
}

// ---------------------------------------------------------------------------
// Kernel B: full loss in ONE kernel. 126 blocks x 256 threads, warp-per-item.
// Independent loads issued up front; last block does the final reduction.
// ---------------------------------------------------------------------------
__global__ __launch_bounds__(256) void loss_kernel(
    const float* __restrict__ cls_logits,   // (bs, ch, C)
    const float* __restrict__ iou_scores,   // (bs, ch, 1)
    const int*   __restrict__ target_ids,   // (bs, ch)
    const int*   __restrict__ map_indices,  // (bs, 2, ch)
    const float* __restrict__ map_ious,     // (bs, ch)
    const float* __restrict__ rand_vals,    // (bs, ch)
    float* __restrict__ out)                // [iou_loss, cls_loss]
{
    const int warp = threadIdx.x >> 5;      // 0..7
    const int lane = threadIdx.x & 31;
    const int item = blockIdx.x * WPB + warp;   // 0..1007 exact

    const int b = item / JCNT;
    const int j = FG_STCH + (item % JCNT);

    // -------- wave 1: all independent loads issued together (cold DRAM) -----
    const int   pj  = __ldg(&map_indices[b * 2 * CH + j]);
    const int   gj  = __ldg(&map_indices[b * 2 * CH + CH + j]);
    const float iou = __ldg(&map_ious[b * CH + j]);
    const float rnd = __ldg(&rand_vals[b * CH + j]);

    // -------- wave 2: loads dependent on pj / gj (issued together) ----------
    const int   tid       = __ldg(&target_ids[b * CH + gj]);
    const float preds_iou = __ldg(&iou_scores[b * CH + pj]);
    const float* row = cls_logits + (size_t)(b * CH + pj) * NC;
    const float x0 = __ldg(&row[lane]);
    const float x1 = __ldg(&row[lane + 32]);
    const float x2 = (lane < NC - 64) ? __ldg(&row[lane + 64]) : -FLT_MAX;
    // mp partials (L2-warm: written by kernel A)
    const float* mpp = &g_maxprob_part[(b * CH + pj) * SPLIT];
    const float mpa = mpp[0], mpb = mpp[1], mpc = mpp[2], mpd = mpp[3];

    // -------- arithmetic --------
    const int cls = max(0, tid - FG_STCH + 1);
    const float mp = fmaxf(fmaxf(mpa, mpb), fmaxf(mpc, mpd));
    const bool remove = (mp < 0.1f) && (rnd < 0.9f);
    const float wght = remove ? 0.0f : ((iou < 0.2f) ? 1.0f : 2.0f);

    const float y = fabsf(preds_iou - iou);
    const float iou_el = (y < 0.1f) ? (y * y * 5.0f) : (y - 0.05f);

    // warp-parallel log-softmax over C=81
    float mx = fmaxf(fmaxf(x0, x1), x2);
#pragma unroll
    for (int o = 16; o > 0; o >>= 1)
        mx = fmaxf(mx, __shfl_xor_sync(0xFFFFFFFFu, mx, o));

    float s = expf(x0 - mx) + expf(x1 - mx);
    if (lane < NC - 64) s += expf(x2 - mx);
#pragma unroll
    for (int o = 16; o > 0; o >>= 1)
        s += __shfl_xor_sync(0xFFFFFFFFu, s, o);

    float v0 = 0.0f, v1 = 0.0f, v2 = 0.0f;
    if (lane == 0) {
        const float ce = -(__ldg(&row[cls]) - mx - logf(s));  // w[cls]==1
        v0 = wght;
        v1 = iou_el * wght;
        v2 = ce * wght;
    }

    // -------- block reduce across 8 warps --------
    __shared__ float s0[WPB], s1[WPB], s2[WPB];
    if (lane == 0) { s0[warp] = v0; s1[warp] = v1; s2[warp] = v2; }
    __syncthreads();

    __shared__ bool is_last;
    if (warp == 0) {
        float a0 = (lane < WPB) ? s0[lane] : 0.0f;
        float a1 = (lane < WPB) ? s1[lane] : 0.0f;
        float a2 = (lane < WPB) ? s2[lane] : 0.0f;
#pragma unroll
        for (int o = WPB / 2; o > 0; o >>= 1) {
            a0 += __shfl_xor_sync(0xFFFFFFFFu, a0, o);
            a1 += __shfl_xor_sync(0xFFFFFFFFu, a1, o);
            a2 += __shfl_xor_sync(0xFFFFFFFFu, a2, o);
        }
        if (lane == 0) {
            g_partial[blockIdx.x * 3 + 0] = a0;
            g_partial[blockIdx.x * 3 + 1] = a1;
            g_partial[blockIdx.x * 3 + 2] = a2;
            __threadfence();
            const int prev = atomicAdd(&g_loss_count, 1);
            is_last = (prev == NLOSS_BLK - 1);
        }
        __syncwarp();

        // last block: deterministic fixed-order final reduction (L2-warm)
        if (is_last) {
            float b0 = 0.0f, b1 = 0.0f, b2 = 0.0f;
#pragma unroll
            for (int k = 0; k < 4; k++) {
                const int i = lane + 32 * k;
                if (i < NLOSS_BLK) {
                    b0 += __ldcg(&g_partial[i * 3 + 0]);
                    b1 += __ldcg(&g_partial[i * 3 + 1]);
                    b2 += __ldcg(&g_partial[i * 3 + 2]);
                }
            }
#pragma unroll
            for (int o = 16; o > 0; o >>= 1) {
                b0 += __shfl_xor_sync(0xFFFFFFFFu, b0, o);
                b1 += __shfl_xor_sync(0xFFFFFFFFu, b1, o);
                b2 += __shfl_xor_sync(0xFFFFFFFFu, b2, o);
            }
            if (lane == 0) {
                const float wsum = b0 + 0.0001f;
                out[0] = b1 / wsum;   // iou_loss
                out[1] = b2 / wsum;   // cls_loss
                g_loss_count = 0;     // reset for next graph replay
            }
        }
    }
}

// ---------------------------------------------------------------------------
extern "C" void kernel_launch(void* const* d_in, const int* in_sizes, int n_in,
                              void* d_out, int out_size) {
    const float* cls_logits     = (const float*)d_in[0];
    const float* iou_scores     = (const float*)d_in[1];
    const int*   target_ids     = (const int*)  d_in[2];
    const int*   map_indices    = (const int*)  d_in[3];
    const float* map_ious       = (const float*)d_in[4];
    const float* pred_mask_prob = (const float*)d_in[5];
    const float* rand_vals      = (const float*)d_in[6];
    float* out = (float*)d_out;

    maxprob_kernel<<<NBLK, 256>>>((const float4*)pred_mask_prob);
    loss_kernel<<<NLOSS_BLK, 256>>>(cls_logits, iou_scores, target_ids,
                                    map_indices, map_ious, rand_vals, out);
}